// round 7
// baseline (speedup 1.0000x reference)
#include <cuda_runtime.h>
#include <cuda_bf16.h>
#include <cstdint>

// ---------------------------------------------------------------------------
// Problem constants
// ---------------------------------------------------------------------------
#define BATCH 32
#define CDIM 384
#define HW 56
#define NPIX 3136
#define NPIXP 3200         // padded pixel count (25 * 128)
#define WS 7
#define NHEAD 12
#define DHEAD 32
#define NWIN 2048
#define NTOK 49
#define KS 1152            // 3 * 384 split K
#define NCH 36             // KS / 32 chunks

#define QS ((size_t)NWIN * NHEAD * NTOK * DHEAD)

// Scratch (device globals are zero-initialized; padding rows read as 0)
__device__ float          g_qkv[3 * NWIN * NHEAD * NTOK * DHEAD];   // 462 MB
__device__ __nv_bfloat16  g_wq[(3 * CDIM) * KS];
__device__ __nv_bfloat16  g_wp[CDIM * KS];
__device__ __nv_bfloat16  g_xT[(size_t)BATCH * NPIXP * KS];         // 236 MB
__device__ __nv_bfloat16  g_attT[(size_t)BATCH * NPIXP * KS];       // 236 MB

// ---------------------------------------------------------------------------
// PTX helpers (base-target instructions only: sm_80-era)
// ---------------------------------------------------------------------------
__device__ __forceinline__ uint32_t smem_u32(const void* p) {
    uint32_t a;
    asm("{ .reg .u64 t; cvta.to.shared.u64 t, %1; cvt.u32.u64 %0, t; }" : "=r"(a) : "l"(p));
    return a;
}
#define CPA(dst, src) \
    asm volatile("cp.async.cg.shared.global [%0], [%1], 16;" :: "r"(dst), "l"(src))
#define CPC() asm volatile("cp.async.commit_group;" ::: "memory")
#define CPW(n) asm volatile("cp.async.wait_group %0;" :: "n"(n) : "memory")

#define LDSM4(r, addr) \
    asm volatile("ldmatrix.sync.aligned.m8n8.x4.shared.b16 {%0,%1,%2,%3}, [%4];" \
        : "=r"((r)[0]), "=r"((r)[1]), "=r"((r)[2]), "=r"((r)[3]) : "r"(addr))

#define MMA16816(d, a, b0, b1) \
    asm volatile("mma.sync.aligned.m16n8k16.row.col.f32.bf16.bf16.f32 " \
        "{%0,%1,%2,%3}, {%4,%5,%6,%7}, {%8,%9}, {%0,%1,%2,%3};" \
        : "+f"((d)[0]), "+f"((d)[1]), "+f"((d)[2]), "+f"((d)[3]) \
        : "r"((a)[0]), "r"((a)[1]), "r"((a)[2]), "r"((a)[3]), "r"(b0), "r"(b1))

// ---------------------------------------------------------------------------
// conv_w: A' = [hi | hi | lo] over K'.  which==0 -> g_wq (1152 rows), else g_wp
// ---------------------------------------------------------------------------
__global__ __launch_bounds__(256) void conv_w_kernel(const float* __restrict__ w,
                                                     int which, int rows)
{
    int idx = blockIdx.x * 256 + threadIdx.x;
    int total = rows * (KS / 2);
    if (idx >= total) return;
    int row = idx / (KS / 2);
    int j   = (idx % (KS / 2)) * 2;
    int blk = j / CDIM;
    int c   = j - blk * CDIM;
    float v0 = w[row * CDIM + c];
    float v1 = w[row * CDIM + c + 1];
    __nv_bfloat16 h0 = __float2bfloat16_rn(v0);
    __nv_bfloat16 h1 = __float2bfloat16_rn(v1);
    __nv_bfloat162 o;
    if (blk == 2) {
        o.x = __float2bfloat16_rn(v0 - __bfloat162float(h0));
        o.y = __float2bfloat16_rn(v1 - __bfloat162float(h1));
    } else {
        o.x = h0; o.y = h1;
    }
    __nv_bfloat16* dst = which ? g_wp : g_wq;
    *(__nv_bfloat162*)(dst + (size_t)row * KS + j) = o;
}

// ---------------------------------------------------------------------------
// conv_x: x[b][c][p] -> g_xT[b][p][k'] bf16, B' = [hi | lo | hi]
// ---------------------------------------------------------------------------
__global__ __launch_bounds__(256) void conv_x_kernel(const float* __restrict__ x)
{
    __shared__ float s[192 * 36];
    const int b  = blockIdx.y;
    const int p0 = blockIdx.x * 32;
    const int tid = threadIdx.x;
    const int pp = tid >> 3, ct = tid & 7;

    __nv_bfloat16* my = g_xT + ((size_t)b * NPIXP + p0 + pp) * KS;

    for (int pass = 0; pass < 2; pass++) {
        const int c0 = pass * 192;
        __syncthreads();
        #pragma unroll
        for (int i = 0; i < 6; i++) {
            int e = tid + i * 256;
            int row = e >> 3, c4 = e & 7;
            float4 v = *(const float4*)(x + ((size_t)(b * CDIM + c0 + row)) * NPIX + p0 + c4 * 4);
            *(float4*)&s[row * 36 + c4 * 4] = v;
        }
        __syncthreads();
        for (int cp = ct; cp < 96; cp += 8) {
            int sl = 2 * cp;
            float v0 = s[sl * 36 + pp];
            float v1 = s[(sl + 1) * 36 + pp];
            int c = c0 + sl;
            __nv_bfloat16 h0 = __float2bfloat16_rn(v0);
            __nv_bfloat16 h1 = __float2bfloat16_rn(v1);
            __nv_bfloat162 hp, lp;
            hp.x = h0; hp.y = h1;
            lp.x = __float2bfloat16_rn(v0 - __bfloat162float(h0));
            lp.y = __float2bfloat16_rn(v1 - __bfloat162float(h1));
            *(__nv_bfloat162*)(my + c)            = hp;
            *(__nv_bfloat162*)(my + CDIM + c)     = lp;
            *(__nv_bfloat162*)(my + 2 * CDIM + c) = hp;
        }
    }
}

// ---------------------------------------------------------------------------
// mma.sync GEMM: D[128 o][128 p] = A'[o][k'] B'[p][k'], K'=1152.
// 128 threads = 4 warps (2m x 2n), warp tile 64x64 = 4x8 m16n8k16 mma.
// Smem-crossbar optimized: A and B each read only 2x per chunk (32KB vs 48KB).
// 3-stage cp.async pipeline, 2 CTAs/SM.
// MODE 0: A=g_wq, B=g_xT,   epilogue -> windowed fp32 qkv scatter (via smem)
// MODE 1: A=g_wp, B=g_attT, epilogue -> out + bias (direct)
// ---------------------------------------------------------------------------
template <int MODE>
__global__ __launch_bounds__(128, 2) void gemm_kernel(const float* __restrict__ b_proj,
                                                      float* __restrict__ out)
{
    __shared__ __align__(128) char smem[49152];   // 3 x (8K A + 8K B); epi 128x65 f32

    const int b   = blockIdx.z;
    const int pt  = blockIdx.x;
    const int ot  = blockIdx.y;
    const int tid = threadIdx.x;
    const int lane = tid & 31, w = tid >> 5;
    const int wm = w >> 1, wn = w & 1;            // 2x2 warp grid

    const uint32_t sbase = smem_u32(smem);

    const __nv_bfloat16* Ag = (MODE == 0 ? g_wq : g_wp) + (size_t)(ot * 128) * KS;
    const __nv_bfloat16* Bg = (MODE == 0 ? g_xT : g_attT)
                              + ((size_t)b * NPIXP + (size_t)pt * 128) * KS;

    // loader: 128 threads; thread covers rows lr, lr+32, lr+64, lr+96 (A and B)
    const int lr = tid >> 2, lg = tid & 3;

    auto load_chunk = [&](int c, int bs) {
        const uint32_t bo = bs * 16384u;
        #pragma unroll
        for (int q = 0; q < 4; q++) {
            const int row = lr + q * 32;
            const uint32_t sw = (uint32_t)((lg ^ (row & 3)) << 4);
            const size_t goff = (size_t)row * KS + c * 32 + lg * 8;
            CPA(sbase + bo + row * 64 + sw,        Ag + goff);
            CPA(sbase + bo + 8192 + row * 64 + sw, Bg + goff);
        }
    };

    // ldmatrix per-thread base addresses (kstep0, buffer0)
    const int blk = lane >> 3, rr = lane & 7;
    uint32_t addrA[4], addrB[4];
    #pragma unroll
    for (int mt = 0; mt < 4; mt++) {
        int m = wm * 64 + mt * 16 + (blk & 1) * 8 + rr;
        addrA[mt] = sbase + m * 64 + (((blk >> 1) ^ (m & 3)) << 4);
    }
    #pragma unroll
    for (int nt2 = 0; nt2 < 4; nt2++) {
        int n = wn * 64 + nt2 * 16 + (blk & 1) * 8 + rr;
        addrB[nt2] = sbase + 8192 + n * 64 + (((blk >> 1) ^ (n & 3)) << 4);
    }

    float acc[4][8][4] = {};

    load_chunk(0, 0); CPC();
    load_chunk(1, 1); CPC();

    int bufc = 0;                                 // (c % 3)
    for (int c = 0; c < NCH; c++) {
        CPW(1);                                   // chunk c landed (FIFO)
        __syncthreads();                          // all warps done with chunk c-1
        if (c + 2 < NCH) {
            int bs = c + 2 - ((c + 2) / 3) * 3;
            load_chunk(c + 2, bs);
        }
        CPC();                                    // one group per iteration

        const uint32_t bo = (uint32_t)bufc * 16384u;
        #pragma unroll
        for (int kstep = 0; kstep < 2; kstep++) {
            const uint32_t kx = kstep * 32;       // XOR: flips swizzle-group bit1
            uint32_t a[4][4];
            #pragma unroll
            for (int mt = 0; mt < 4; mt++)
                LDSM4(a[mt], (addrA[mt] + bo) ^ kx);
            #pragma unroll
            for (int nt2 = 0; nt2 < 4; nt2++) {
                uint32_t r[4];
                LDSM4(r, (addrB[nt2] + bo) ^ kx);
                #pragma unroll
                for (int mt = 0; mt < 4; mt++) {
                    MMA16816(acc[mt][nt2 * 2 + 0], a[mt], r[0], r[2]);
                    MMA16816(acc[mt][nt2 * 2 + 1], a[mt], r[1], r[3]);
                }
            }
        }
        bufc = (bufc == 2) ? 0 : bufc + 1;
    }

    const int tq = lane >> 2, tr = lane & 3;

    if (MODE == 0) {
        // Stage to smem, then coalesced 128B scatter into windowed layout.
        float* sf = (float*)smem;
        #pragma unroll
        for (int pass = 0; pass < 2; pass++) {
            __syncthreads();
            if (wn == pass) {
                #pragma unroll
                for (int mt = 0; mt < 4; mt++)
                    #pragma unroll
                    for (int nt = 0; nt < 8; nt++) {
                        int row = wm * 64 + mt * 16 + tq;
                        int col = nt * 8 + tr * 2;
                        sf[row * 65 + col]           = acc[mt][nt][0];
                        sf[row * 65 + col + 1]       = acc[mt][nt][1];
                        sf[(row + 8) * 65 + col]     = acc[mt][nt][2];
                        sf[(row + 8) * 65 + col + 1] = acc[mt][nt][3];
                    }
            }
            __syncthreads();
            #pragma unroll 4
            for (int i = 0; i < 64; i++) {
                int unit = w + 4 * i;             // 0..255
                int col = unit & 63, seg = unit >> 6;
                int p = pt * 128 + pass * 64 + col;
                if (p < NPIX) {
                    float v = sf[(seg * 32 + lane) * 65 + col];
                    int o0 = ot * 128 + seg * 32;
                    int qi = o0 / CDIM;
                    int head = (o0 % CDIM) >> 5;
                    int y = p / HW, xx = p % HW;
                    int win = b * 64 + (y / WS) * 8 + xx / WS;
                    int tok = (y % WS) * WS + xx % WS;
                    g_qkv[(size_t)qi * QS +
                          ((size_t)win * NHEAD + head) * (NTOK * DHEAD) +
                          tok * DHEAD + lane] = v;
                }
            }
        }
    } else {
        #pragma unroll
        for (int mt = 0; mt < 4; mt++) {
            int o = ot * 128 + wm * 64 + mt * 16 + tq;
            float bias0 = __ldg(b_proj + o);
            float bias8 = __ldg(b_proj + o + 8);
            float* r0 = out + ((size_t)b * CDIM + o) * NPIX;
            float* r8 = r0 + (size_t)8 * NPIX;
            #pragma unroll
            for (int nt = 0; nt < 8; nt++) {
                int p = pt * 128 + wn * 64 + nt * 8 + tr * 2;
                if (p < NPIX) {
                    *(float2*)(r0 + p) = make_float2(acc[mt][nt][0] + bias0,
                                                     acc[mt][nt][1] + bias0);
                    *(float2*)(r8 + p) = make_float2(acc[mt][nt][2] + bias8,
                                                     acc[mt][nt][3] + bias8);
                }
            }
        }
    }
}

// ---------------------------------------------------------------------------
// attention: fp32 windowed in, split-bf16 transposed out (g_attT).
// Register-tiled 4x4 micro-GEMMs; q/k transposed in smem for LDS.128.
// ---------------------------------------------------------------------------
__global__ __launch_bounds__(128) void attn_kernel(const float* __restrict__ bias_table)
{
    const int wh   = blockIdx.x;
    const int win  = wh / NHEAD;
    const int head = wh % NHEAD;
    const int tid  = threadIdx.x;

    __shared__ float qT[32 * 56];     // [d][tok], cols 49..55 zero
    __shared__ float kT[32 * 56];
    __shared__ float vs[NTOK * 32];   // [tok][d]
    __shared__ float s[52 * 53];      // logits / probs, stride 53
    __shared__ float sbias[169];

    const float scale = 0.17677669529663687f;
    const size_t base = (((size_t)win * NHEAD + head) * NTOK) * DHEAD;
    const float4* qp = (const float4*)(g_qkv + base);
    const float4* kp = (const float4*)(g_qkv + QS + base);
    const float4* vp = (const float4*)(g_qkv + 2 * QS + base);

    // zero pad columns 49..55 of qT, kT (read by i0=48 tiles)
    for (int e = tid; e < 448; e += 128) {
        int a = e / 224, rem = e % 224;
        int r = rem / 7, c = 49 + rem % 7;
        (a ? kT : qT)[r * 56 + c] = 0.f;
    }
    for (int e = tid; e < 169; e += 128)
        sbias[e] = bias_table[e * NHEAD + head];

    for (int e = tid; e < 392; e += 128) {
        int tok = e >> 3, d4 = (e & 7) * 4;
        float4 q4 = qp[e];
        qT[(d4 + 0) * 56 + tok] = q4.x * scale;
        qT[(d4 + 1) * 56 + tok] = q4.y * scale;
        qT[(d4 + 2) * 56 + tok] = q4.z * scale;
        qT[(d4 + 3) * 56 + tok] = q4.w * scale;
        float4 k4 = kp[e];
        kT[(d4 + 0) * 56 + tok] = k4.x;
        kT[(d4 + 1) * 56 + tok] = k4.y;
        kT[(d4 + 2) * 56 + tok] = k4.z;
        kT[(d4 + 3) * 56 + tok] = k4.w;
        ((float4*)vs)[e] = vp[e];
    }
    __syncthreads();

    // S = (q^T)^T (k^T): 13x13 tiles of 4x4; 2 x LDS.128 per 16 FMA
    for (int t = tid; t < 169; t += 128) {
        const int i0 = (t / 13) * 4, j0 = (t % 13) * 4;
        float acc[4][4] = {};
        #pragma unroll
        for (int d = 0; d < 32; d++) {
            float4 q4 = *(const float4*)&qT[d * 56 + i0];
            float4 k4 = *(const float4*)&kT[d * 56 + j0];
            float qa[4] = {q4.x, q4.y, q4.z, q4.w};
            float ka[4] = {k4.x, k4.y, k4.z, k4.w};
            #pragma unroll
            for (int ii = 0; ii < 4; ii++)
                #pragma unroll
                for (int jj = 0; jj < 4; jj++)
                    acc[ii][jj] += qa[ii] * ka[jj];
        }
        #pragma unroll
        for (int ii = 0; ii < 4; ii++) {
            int i = i0 + ii;
            #pragma unroll
            for (int jj = 0; jj < 4; jj++) {
                int j = j0 + jj;
                float v = 0.f;
                if (i < NTOK && j < NTOK) {
                    int bidx = (i / WS - j / WS + 6) * 13 + (i % WS - j % WS + 6);
                    v = acc[ii][jj] + sbias[bidx];
                }
                s[i * 53 + j] = v;
            }
        }
    }
    __syncthreads();

    if (tid < NTOK) {
        float m = -1e30f;
        #pragma unroll
        for (int j = 0; j < NTOK; j++) m = fmaxf(m, s[tid * 53 + j]);
        float sum = 0.f;
        #pragma unroll
        for (int j = 0; j < NTOK; j++) {
            float ev = __expf(s[tid * 53 + j] - m);
            s[tid * 53 + j] = ev;
            sum += ev;
        }
        float inv = 1.f / sum;
        #pragma unroll
        for (int j = 0; j < NTOK; j++) s[tid * 53 + j] *= inv;
    }
    __syncthreads();

    // O = P @ V: 13 i-tiles x 8 d-quads = 104 threads, 4x4 register tiles
    if (tid < 104) {
        const int i0 = (tid >> 3) * 4, d0 = (tid & 7) * 4;
        float acc[4][4] = {};
        #pragma unroll 7
        for (int m = 0; m < NTOK; m++) {
            float4 v4 = *(const float4*)&vs[m * 32 + d0];
            float va[4] = {v4.x, v4.y, v4.z, v4.w};
            float sa[4];
            #pragma unroll
            for (int ii = 0; ii < 4; ii++) sa[ii] = s[(i0 + ii) * 53 + m];
            #pragma unroll
            for (int ii = 0; ii < 4; ii++)
                #pragma unroll
                for (int jj = 0; jj < 4; jj++)
                    acc[ii][jj] += sa[ii] * va[jj];
        }

        const int b_img = win >> 6;
        const int wl = win & 63;
        const int wy = wl >> 3, wx = wl & 7;
        #pragma unroll
        for (int ii = 0; ii < 4; ii++) {
            int i = i0 + ii;
            if (i < NTOK) {
                int y  = wy * WS + i / WS;
                int xx = wx * WS + i % WS;
                __nv_bfloat16* row = g_attT
                    + ((size_t)b_img * NPIXP + y * HW + xx) * KS + head * DHEAD + d0;
                #pragma unroll
                for (int p2 = 0; p2 < 2; p2++) {
                    float a0 = acc[ii][2 * p2];
                    float a1 = acc[ii][2 * p2 + 1];
                    __nv_bfloat16 h0 = __float2bfloat16_rn(a0);
                    __nv_bfloat16 h1 = __float2bfloat16_rn(a1);
                    __nv_bfloat162 hp, lp;
                    hp.x = h0; hp.y = h1;
                    lp.x = __float2bfloat16_rn(a0 - __bfloat162float(h0));
                    lp.y = __float2bfloat16_rn(a1 - __bfloat162float(h1));
                    *(__nv_bfloat162*)(row + 2 * p2)            = hp;
                    *(__nv_bfloat162*)(row + CDIM + 2 * p2)     = lp;
                    *(__nv_bfloat162*)(row + 2 * CDIM + 2 * p2) = hp;
                }
            }
        }
    }
}

// ---------------------------------------------------------------------------
extern "C" void kernel_launch(void* const* d_in, const int* in_sizes, int n_in,
                              void* d_out, int out_size)
{
    const float* x          = (const float*)d_in[0];
    const float* w_qkv      = (const float*)d_in[1];
    const float* bias_table = (const float*)d_in[2];
    const float* w_proj     = (const float*)d_in[3];
    const float* b_proj     = (const float*)d_in[4];
    float* out = (float*)d_out;

    conv_w_kernel<<<(1152 * (KS / 2) + 255) / 256, 256>>>(w_qkv, 0, 1152);
    conv_w_kernel<<<(384 * (KS / 2) + 255) / 256, 256>>>(w_proj, 1, 384);
    conv_x_kernel<<<dim3(NPIX / 32, BATCH), 256>>>(x);

    gemm_kernel<0><<<dim3(NPIXP / 128, 9, BATCH), 128>>>(nullptr, nullptr);

    attn_kernel<<<NWIN * NHEAD, 128>>>(bias_table);

    gemm_kernel<1><<<dim3(NPIXP / 128, 3, BATCH), 128>>>(b_proj, out);
}

// round 9
// speedup vs baseline: 1.7031x; 1.7031x over previous
#include <cuda_runtime.h>
#include <cuda_fp16.h>
#include <cstdint>

// ---------------------------------------------------------------------------
// Problem constants
// ---------------------------------------------------------------------------
#define BATCH 32
#define CDIM 384
#define HW 56
#define NPIX 3136
#define NPIXP 3200         // padded pixel count (25 * 128)
#define WS 7
#define NHEAD 12
#define DHEAD 32
#define NWIN 2048
#define NTOK 49
#define KS 384             // single fp16 GEMM K
#define NCH 12             // KS / 32 chunks

#define QS ((size_t)NWIN * NHEAD * NTOK * DHEAD)

// Scratch (device globals are zero-initialized; padding rows read as 0)
__device__ float   g_qkv[3 * NWIN * NHEAD * NTOK * DHEAD];   // 462 MB
__device__ __half  g_wq[(3 * CDIM) * KS];
__device__ __half  g_wp[CDIM * KS];
__device__ __half  g_xT[(size_t)BATCH * NPIXP * KS];         // 77 MB
__device__ __half  g_attT[(size_t)BATCH * NPIXP * KS];       // 77 MB

// ---------------------------------------------------------------------------
// PTX helpers (base-target instructions only: sm_80-era)
// ---------------------------------------------------------------------------
__device__ __forceinline__ uint32_t smem_u32(const void* p) {
    uint32_t a;
    asm("{ .reg .u64 t; cvta.to.shared.u64 t, %1; cvt.u32.u64 %0, t; }" : "=r"(a) : "l"(p));
    return a;
}
#define CPA(dst, src) \
    asm volatile("cp.async.cg.shared.global [%0], [%1], 16;" :: "r"(dst), "l"(src))
#define CPC() asm volatile("cp.async.commit_group;" ::: "memory")
#define CPW(n) asm volatile("cp.async.wait_group %0;" :: "n"(n) : "memory")

#define LDSM4(r, addr) \
    asm volatile("ldmatrix.sync.aligned.m8n8.x4.shared.b16 {%0,%1,%2,%3}, [%4];" \
        : "=r"((r)[0]), "=r"((r)[1]), "=r"((r)[2]), "=r"((r)[3]) : "r"(addr))

#define MMA16816(d, a, b0, b1) \
    asm volatile("mma.sync.aligned.m16n8k16.row.col.f32.f16.f16.f32 " \
        "{%0,%1,%2,%3}, {%4,%5,%6,%7}, {%8,%9}, {%0,%1,%2,%3};" \
        : "+f"((d)[0]), "+f"((d)[1]), "+f"((d)[2]), "+f"((d)[3]) \
        : "r"((a)[0]), "r"((a)[1]), "r"((a)[2]), "r"((a)[3]), "r"(b0), "r"(b1))

// ---------------------------------------------------------------------------
// conv_w: fp32 weight [rows][384] -> fp16, same layout.
// which==0 -> g_wq (1152 rows), which==1 -> g_wp (384 rows)
// ---------------------------------------------------------------------------
__global__ __launch_bounds__(256) void conv_w_kernel(const float* __restrict__ w,
                                                     int which, int rows)
{
    int idx = blockIdx.x * 256 + threadIdx.x;
    int total = rows * (KS / 2);
    if (idx >= total) return;
    const float2 v = *(const float2*)(w + idx * 2);
    __half* dst = which ? g_wp : g_wq;
    *(__half2*)(dst + idx * 2) = __floats2half2_rn(v.x, v.y);
}

// ---------------------------------------------------------------------------
// conv_x: x[b][c][p] (fp32) -> g_xT[b][p][c] (fp16 transposed)
// block tile: 32 pixels x 384 channels (two passes of 192c through smem)
// ---------------------------------------------------------------------------
__global__ __launch_bounds__(256) void conv_x_kernel(const float* __restrict__ x)
{
    __shared__ float s[192 * 36];
    const int b  = blockIdx.y;
    const int p0 = blockIdx.x * 32;
    const int tid = threadIdx.x;
    const int pp = tid >> 3, ct = tid & 7;

    __half* my = g_xT + ((size_t)b * NPIXP + p0 + pp) * KS;

    for (int pass = 0; pass < 2; pass++) {
        const int c0 = pass * 192;
        __syncthreads();
        #pragma unroll
        for (int i = 0; i < 6; i++) {
            int e = tid + i * 256;
            int row = e >> 3, c4 = e & 7;
            float4 v = *(const float4*)(x + ((size_t)(b * CDIM + c0 + row)) * NPIX + p0 + c4 * 4);
            *(float4*)&s[row * 36 + c4 * 4] = v;
        }
        __syncthreads();
        for (int cp = ct; cp < 96; cp += 8) {
            int sl = 2 * cp;
            float v0 = s[sl * 36 + pp];
            float v1 = s[(sl + 1) * 36 + pp];
            *(__half2*)(my + c0 + sl) = __floats2half2_rn(v0, v1);
        }
    }
}

// ---------------------------------------------------------------------------
// mma.sync GEMM: D[128 o][128 p] = A[o][k] B[p][k], K=384, fp16 in, fp32 acc.
// 256 threads = 8 warps (4m x 2n), warp tile 32x64 = 2x8 m16n8k16 mma.
// 3-stage cp.async pipeline (16KB stages), 2 CTAs/SM.
// MODE 0: A=g_wq, B=g_xT,   epilogue -> windowed fp32 qkv scatter (via smem)
// MODE 1: A=g_wp, B=g_attT, epilogue -> out + bias (direct)
// ---------------------------------------------------------------------------
template <int MODE>
__global__ __launch_bounds__(256, 2) void gemm_kernel(const float* __restrict__ b_proj,
                                                      float* __restrict__ out)
{
    __shared__ __align__(128) char smem[49152];   // 3 x (8K A + 8K B); epi 128x65 f32

    const int b   = blockIdx.z;
    const int pt  = blockIdx.x;
    const int ot  = blockIdx.y;
    const int tid = threadIdx.x;
    const int lane = tid & 31, w = tid >> 5;
    const int wm = w >> 1, wn = w & 1;

    const uint32_t sbase = smem_u32(smem);

    const __half* Ag = (MODE == 0 ? g_wq : g_wp) + (size_t)(ot * 128) * KS;
    const __half* Bg = (MODE == 0 ? g_xT : g_attT)
                       + ((size_t)b * NPIXP + (size_t)pt * 128) * KS;

    // loader mapping: 512 16B groups per tile, 2 per thread (rows r, r+64)
    const int lr = tid >> 2, lg = tid & 3;
    const uint32_t sA = sbase + lr * 64 + ((lg ^ (lr & 3)) << 4);
    const uint32_t sB = sA + 8192;
    const __half* Asrc = Ag + (size_t)lr * KS + lg * 8;
    const __half* Bsrc = Bg + (size_t)lr * KS + lg * 8;

    auto load_chunk = [&](int c, int bs) {
        const uint32_t bo = bs * 16384u;
        const __half* a = Asrc + c * 32;
        CPA(sA + bo, a);
        CPA(sA + bo + 4096, a + (size_t)64 * KS);
        const __half* bb = Bsrc + c * 32;
        CPA(sB + bo, bb);
        CPA(sB + bo + 4096, bb + (size_t)64 * KS);
    };

    // ldmatrix per-thread base addresses (kstep0, buffer0)
    const int blk = lane >> 3, rr = lane & 7;
    uint32_t addrA[2], addrB[4];
    #pragma unroll
    for (int mt = 0; mt < 2; mt++) {
        int m = wm * 32 + mt * 16 + (blk & 1) * 8 + rr;
        addrA[mt] = sbase + m * 64 + (((blk >> 1) ^ (m & 3)) << 4);
    }
    #pragma unroll
    for (int nt2 = 0; nt2 < 4; nt2++) {
        int n = wn * 64 + nt2 * 16 + (blk & 1) * 8 + rr;
        addrB[nt2] = sbase + 8192 + n * 64 + (((blk >> 1) ^ (n & 3)) << 4);
    }

    float acc[2][8][4] = {};

    load_chunk(0, 0); CPC();
    load_chunk(1, 1); CPC();

    int bufc = 0;                                 // (c % 3)
    for (int c = 0; c < NCH; c++) {
        CPW(1);                                   // chunk c landed (FIFO)
        __syncthreads();                          // all warps done with chunk c-1
        if (c + 2 < NCH) {
            int bs = c + 2 - ((c + 2) / 3) * 3;
            load_chunk(c + 2, bs);
        }
        CPC();                                    // one group per iteration

        const uint32_t bo = (uint32_t)bufc * 16384u;
        #pragma unroll
        for (int kstep = 0; kstep < 2; kstep++) {
            const uint32_t kx = kstep * 32;       // XOR: flips swizzle-group bit1
            uint32_t a[2][4];
            #pragma unroll
            for (int mt = 0; mt < 2; mt++)
                LDSM4(a[mt], (addrA[mt] + bo) ^ kx);
            #pragma unroll
            for (int nt2 = 0; nt2 < 4; nt2++) {
                uint32_t r[4];
                LDSM4(r, (addrB[nt2] + bo) ^ kx);
                #pragma unroll
                for (int mt = 0; mt < 2; mt++) {
                    MMA16816(acc[mt][nt2 * 2 + 0], a[mt], r[0], r[2]);
                    MMA16816(acc[mt][nt2 * 2 + 1], a[mt], r[1], r[3]);
                }
            }
        }
        bufc = (bufc == 2) ? 0 : bufc + 1;
    }

    const int tq = lane >> 2, tr = lane & 3;

    if (MODE == 0) {
        // Stage to smem, then coalesced 128B scatter into windowed layout.
        float* sf = (float*)smem;
        #pragma unroll
        for (int pass = 0; pass < 2; pass++) {
            __syncthreads();
            if (wn == pass) {
                #pragma unroll
                for (int mt = 0; mt < 2; mt++)
                    #pragma unroll
                    for (int nt = 0; nt < 8; nt++) {
                        int row = wm * 32 + mt * 16 + tq;
                        int col = nt * 8 + tr * 2;
                        sf[row * 65 + col]           = acc[mt][nt][0];
                        sf[row * 65 + col + 1]       = acc[mt][nt][1];
                        sf[(row + 8) * 65 + col]     = acc[mt][nt][2];
                        sf[(row + 8) * 65 + col + 1] = acc[mt][nt][3];
                    }
            }
            __syncthreads();
            #pragma unroll 4
            for (int i = 0; i < 32; i++) {
                int unit = w + 8 * i;
                int col = unit & 63, seg = unit >> 6;
                int p = pt * 128 + pass * 64 + col;
                if (p < NPIX) {
                    float v = sf[(seg * 32 + lane) * 65 + col];
                    int o0 = ot * 128 + seg * 32;
                    int qi = o0 / CDIM;
                    int head = (o0 % CDIM) >> 5;
                    int y = p / HW, xx = p % HW;
                    int win = b * 64 + (y / WS) * 8 + xx / WS;
                    int tok = (y % WS) * WS + xx % WS;
                    g_qkv[(size_t)qi * QS +
                          ((size_t)win * NHEAD + head) * (NTOK * DHEAD) +
                          tok * DHEAD + lane] = v;
                }
            }
        }
    } else {
        #pragma unroll
        for (int mt = 0; mt < 2; mt++) {
            int o = ot * 128 + wm * 32 + mt * 16 + tq;
            float bias0 = __ldg(b_proj + o);
            float bias8 = __ldg(b_proj + o + 8);
            float* r0 = out + ((size_t)b * CDIM + o) * NPIX;
            float* r8 = r0 + (size_t)8 * NPIX;
            #pragma unroll
            for (int nt = 0; nt < 8; nt++) {
                int p = pt * 128 + wn * 64 + nt * 8 + tr * 2;
                if (p < NPIX) {
                    *(float2*)(r0 + p) = make_float2(acc[mt][nt][0] + bias0,
                                                     acc[mt][nt][1] + bias0);
                    *(float2*)(r8 + p) = make_float2(acc[mt][nt][2] + bias8,
                                                     acc[mt][nt][3] + bias8);
                }
            }
        }
    }
}

// ---------------------------------------------------------------------------
// attention: fp32 windowed in, fp16 transposed out (g_attT).
// Register-tiled 4x4 micro-GEMMs; q/k transposed in smem for LDS.128.
// ---------------------------------------------------------------------------
__global__ __launch_bounds__(128) void attn_kernel(const float* __restrict__ bias_table)
{
    const int wh   = blockIdx.x;
    const int win  = wh / NHEAD;
    const int head = wh % NHEAD;
    const int tid  = threadIdx.x;

    __shared__ float qT[32 * 56];     // [d][tok], cols 49..55 zero
    __shared__ float kT[32 * 56];
    __shared__ float vs[NTOK * 32];   // [tok][d]
    __shared__ float s[52 * 53];      // logits / probs, stride 53
    __shared__ float sbias[169];

    const float scale = 0.17677669529663687f;
    const size_t base = (((size_t)win * NHEAD + head) * NTOK) * DHEAD;
    const float4* qp = (const float4*)(g_qkv + base);
    const float4* kp = (const float4*)(g_qkv + QS + base);
    const float4* vp = (const float4*)(g_qkv + 2 * QS + base);

    // zero pad columns 49..55 of qT, kT (read by i0=48 tiles)
    for (int e = tid; e < 448; e += 128) {
        int a = e / 224, rem = e % 224;
        int r = rem / 7, c = 49 + rem % 7;
        (a ? kT : qT)[r * 56 + c] = 0.f;
    }
    for (int e = tid; e < 169; e += 128)
        sbias[e] = bias_table[e * NHEAD + head];

    for (int e = tid; e < 392; e += 128) {
        int tok = e >> 3, d4 = (e & 7) * 4;
        float4 q4 = qp[e];
        qT[(d4 + 0) * 56 + tok] = q4.x * scale;
        qT[(d4 + 1) * 56 + tok] = q4.y * scale;
        qT[(d4 + 2) * 56 + tok] = q4.z * scale;
        qT[(d4 + 3) * 56 + tok] = q4.w * scale;
        float4 k4 = kp[e];
        kT[(d4 + 0) * 56 + tok] = k4.x;
        kT[(d4 + 1) * 56 + tok] = k4.y;
        kT[(d4 + 2) * 56 + tok] = k4.z;
        kT[(d4 + 3) * 56 + tok] = k4.w;
        ((float4*)vs)[e] = vp[e];
    }
    __syncthreads();

    // S = (q^T)^T (k^T): 13x13 tiles of 4x4; 2 x LDS.128 per 16 FMA
    for (int t = tid; t < 169; t += 128) {
        const int i0 = (t / 13) * 4, j0 = (t % 13) * 4;
        float acc[4][4] = {};
        #pragma unroll
        for (int d = 0; d < 32; d++) {
            float4 q4 = *(const float4*)&qT[d * 56 + i0];
            float4 k4 = *(const float4*)&kT[d * 56 + j0];
            float qa[4] = {q4.x, q4.y, q4.z, q4.w};
            float ka[4] = {k4.x, k4.y, k4.z, k4.w};
            #pragma unroll
            for (int ii = 0; ii < 4; ii++)
                #pragma unroll
                for (int jj = 0; jj < 4; jj++)
                    acc[ii][jj] += qa[ii] * ka[jj];
        }
        #pragma unroll
        for (int ii = 0; ii < 4; ii++) {
            int i = i0 + ii;
            #pragma unroll
            for (int jj = 0; jj < 4; jj++) {
                int j = j0 + jj;
                float v = 0.f;
                if (i < NTOK && j < NTOK) {
                    int bidx = (i / WS - j / WS + 6) * 13 + (i % WS - j % WS + 6);
                    v = acc[ii][jj] + sbias[bidx];
                }
                s[i * 53 + j] = v;
            }
        }
    }
    __syncthreads();

    if (tid < NTOK) {
        float m = -1e30f;
        #pragma unroll
        for (int j = 0; j < NTOK; j++) m = fmaxf(m, s[tid * 53 + j]);
        float sum = 0.f;
        #pragma unroll
        for (int j = 0; j < NTOK; j++) {
            float ev = __expf(s[tid * 53 + j] - m);
            s[tid * 53 + j] = ev;
            sum += ev;
        }
        float inv = 1.f / sum;
        #pragma unroll
        for (int j = 0; j < NTOK; j++) s[tid * 53 + j] *= inv;
    }
    __syncthreads();

    // O = P @ V: 13 i-tiles x 8 d-quads = 104 threads, 4x4 register tiles
    if (tid < 104) {
        const int i0 = (tid >> 3) * 4, d0 = (tid & 7) * 4;
        float acc[4][4] = {};
        #pragma unroll 7
        for (int m = 0; m < NTOK; m++) {
            float4 v4 = *(const float4*)&vs[m * 32 + d0];
            float va[4] = {v4.x, v4.y, v4.z, v4.w};
            float sa[4];
            #pragma unroll
            for (int ii = 0; ii < 4; ii++) sa[ii] = s[(i0 + ii) * 53 + m];
            #pragma unroll
            for (int ii = 0; ii < 4; ii++)
                #pragma unroll
                for (int jj = 0; jj < 4; jj++)
                    acc[ii][jj] += sa[ii] * va[jj];
        }

        const int b_img = win >> 6;
        const int wl = win & 63;
        const int wy = wl >> 3, wx = wl & 7;
        #pragma unroll
        for (int ii = 0; ii < 4; ii++) {
            int i = i0 + ii;
            if (i < NTOK) {
                int y  = wy * WS + i / WS;
                int xx = wx * WS + i % WS;
                __half* row = g_attT
                    + ((size_t)b_img * NPIXP + y * HW + xx) * KS + head * DHEAD + d0;
                *(__half2*)(row)     = __floats2half2_rn(acc[ii][0], acc[ii][1]);
                *(__half2*)(row + 2) = __floats2half2_rn(acc[ii][2], acc[ii][3]);
            }
        }
    }
}

// ---------------------------------------------------------------------------
extern "C" void kernel_launch(void* const* d_in, const int* in_sizes, int n_in,
                              void* d_out, int out_size)
{
    const float* x          = (const float*)d_in[0];
    const float* w_qkv      = (const float*)d_in[1];
    const float* bias_table = (const float*)d_in[2];
    const float* w_proj     = (const float*)d_in[3];
    const float* b_proj     = (const float*)d_in[4];
    float* out = (float*)d_out;

    conv_w_kernel<<<(1152 * (KS / 2) + 255) / 256, 256>>>(w_qkv, 0, 1152);
    conv_w_kernel<<<(384 * (KS / 2) + 255) / 256, 256>>>(w_proj, 1, 384);
    conv_x_kernel<<<dim3(NPIX / 32, BATCH), 256>>>(x);

    gemm_kernel<0><<<dim3(NPIXP / 128, 9, BATCH), 256>>>(nullptr, nullptr);

    attn_kernel<<<NWIN * NHEAD, 128>>>(bias_table);

    gemm_kernel<1><<<dim3(NPIXP / 128, 3, BATCH), 256>>>(b_proj, out);
}

// round 14
// speedup vs baseline: 2.0053x; 1.1775x over previous
#include <cuda_runtime.h>
#include <cuda_fp16.h>
#include <cstdint>

// ---------------------------------------------------------------------------
// Problem constants
// ---------------------------------------------------------------------------
#define BATCH 32
#define CDIM 384
#define HW 56
#define NPIX 3136
#define NPIXP 3200         // padded pixel count (25 * 128)
#define WS 7
#define NHEAD 12
#define DHEAD 32
#define NWIN 2048
#define NTOK 49
#define KS 384             // single fp16 GEMM K
#define NCH 12             // KS / 32 chunks

#define QS ((size_t)NWIN * NHEAD * NTOK * DHEAD)

// Scratch (device globals are zero-initialized; padding rows read as 0)
__device__ float   g_qkv[3 * NWIN * NHEAD * NTOK * DHEAD];   // 462 MB
__device__ __half  g_wq[(3 * CDIM) * KS];
__device__ __half  g_wp[CDIM * KS];
__device__ __half  g_xT[(size_t)BATCH * NPIXP * KS];         // 77 MB
__device__ __half  g_attT[(size_t)BATCH * NPIXP * KS];       // 77 MB

// ---------------------------------------------------------------------------
// PTX helpers (base-target instructions only: sm_80-era)
// ---------------------------------------------------------------------------
__device__ __forceinline__ uint32_t smem_u32(const void* p) {
    uint32_t a;
    asm("{ .reg .u64 t; cvta.to.shared.u64 t, %1; cvt.u32.u64 %0, t; }" : "=r"(a) : "l"(p));
    return a;
}
#define CPA(dst, src) \
    asm volatile("cp.async.cg.shared.global [%0], [%1], 16;" :: "r"(dst), "l"(src))
#define CPC() asm volatile("cp.async.commit_group;" ::: "memory")
#define CPW(n) asm volatile("cp.async.wait_group %0;" :: "n"(n) : "memory")

#define LDSM4(r, addr) \
    asm volatile("ldmatrix.sync.aligned.m8n8.x4.shared.b16 {%0,%1,%2,%3}, [%4];" \
        : "=r"((r)[0]), "=r"((r)[1]), "=r"((r)[2]), "=r"((r)[3]) : "r"(addr))

#define MMA16816(d, a, b0, b1) \
    asm volatile("mma.sync.aligned.m16n8k16.row.col.f32.f16.f16.f32 " \
        "{%0,%1,%2,%3}, {%4,%5,%6,%7}, {%8,%9}, {%0,%1,%2,%3};" \
        : "+f"((d)[0]), "+f"((d)[1]), "+f"((d)[2]), "+f"((d)[3]) \
        : "r"((a)[0]), "r"((a)[1]), "r"((a)[2]), "r"((a)[3]), "r"(b0), "r"(b1))

// ---------------------------------------------------------------------------
// conv_w: fp32 weight [rows][384] -> fp16, same layout.
// which==0 -> g_wq (1152 rows), which==1 -> g_wp (384 rows)
// ---------------------------------------------------------------------------
__global__ __launch_bounds__(256) void conv_w_kernel(const float* __restrict__ w,
                                                     int which, int rows)
{
    int idx = blockIdx.x * 256 + threadIdx.x;
    int total = rows * (KS / 2);
    if (idx >= total) return;
    const float2 v = *(const float2*)(w + idx * 2);
    __half* dst = which ? g_wp : g_wq;
    *(__half2*)(dst + idx * 2) = __floats2half2_rn(v.x, v.y);
}

// ---------------------------------------------------------------------------
// conv_x: x[b][c][p] (fp32) -> g_xT[b][p][c] (fp16 transposed)
// block tile: 32 pixels x 384 channels (two passes of 192c through smem)
// ---------------------------------------------------------------------------
__global__ __launch_bounds__(256) void conv_x_kernel(const float* __restrict__ x)
{
    __shared__ float s[192 * 36];
    const int b  = blockIdx.y;
    const int p0 = blockIdx.x * 32;
    const int tid = threadIdx.x;
    const int pp = tid >> 3, ct = tid & 7;

    __half* my = g_xT + ((size_t)b * NPIXP + p0 + pp) * KS;

    for (int pass = 0; pass < 2; pass++) {
        const int c0 = pass * 192;
        __syncthreads();
        #pragma unroll
        for (int i = 0; i < 6; i++) {
            int e = tid + i * 256;
            int row = e >> 3, c4 = e & 7;
            float4 v = *(const float4*)(x + ((size_t)(b * CDIM + c0 + row)) * NPIX + p0 + c4 * 4);
            *(float4*)&s[row * 36 + c4 * 4] = v;
        }
        __syncthreads();
        for (int cp = ct; cp < 96; cp += 8) {
            int sl = 2 * cp;
            float v0 = s[sl * 36 + pp];
            float v1 = s[(sl + 1) * 36 + pp];
            *(__half2*)(my + c0 + sl) = __floats2half2_rn(v0, v1);
        }
    }
}

// ---------------------------------------------------------------------------
// mma.sync GEMM: D[128 o][128 p] = A[o][k] B[p][k], K=384, fp16 in, fp32 acc.
// 256 threads = 8 warps (4m x 2n), warp tile 32x64 = 2x8 m16n8k16 mma.
// Fully-unrolled 12-chunk mainloop, 3-stage cp.async pipeline, 2 CTAs/SM.
// MODE 0: A=g_wq, B=g_xT,   epilogue -> windowed fp32 qkv scatter (via smem)
// MODE 1: A=g_wp, B=g_attT, epilogue -> out + bias (direct)
// ---------------------------------------------------------------------------
template <int MODE>
__global__ __launch_bounds__(256, 2) void gemm_kernel(const float* __restrict__ b_proj,
                                                      float* __restrict__ out)
{
    __shared__ __align__(128) char smem[49152];   // 3 x (8K A + 8K B); epi 128x65 f32

    const int b   = blockIdx.z;
    const int pt  = blockIdx.x;
    const int ot  = blockIdx.y;
    const int tid = threadIdx.x;
    const int lane = tid & 31, w = tid >> 5;
    const int wm = w >> 1, wn = w & 1;

    const uint32_t sbase = smem_u32(smem);

    const __half* Ag = (MODE == 0 ? g_wq : g_wp) + (size_t)(ot * 128) * KS;
    const __half* Bg = (MODE == 0 ? g_xT : g_attT)
                       + ((size_t)b * NPIXP + (size_t)pt * 128) * KS;

    // loader mapping: 512 16B groups per tile, 2 per thread (rows r, r+64)
    const int lr = tid >> 2, lg = tid & 3;
    const uint32_t sA = sbase + lr * 64 + ((lg ^ (lr & 3)) << 4);
    const uint32_t sB = sA + 8192;
    const __half* Asrc = Ag + (size_t)lr * KS + lg * 8;
    const __half* Bsrc = Bg + (size_t)lr * KS + lg * 8;

    auto load_chunk = [&](int c, uint32_t bo) {
        const __half* a = Asrc + c * 32;
        CPA(sA + bo, a);
        CPA(sA + bo + 4096, a + (size_t)64 * KS);
        const __half* bb = Bsrc + c * 32;
        CPA(sB + bo, bb);
        CPA(sB + bo + 4096, bb + (size_t)64 * KS);
    };

    // ldmatrix per-thread base addresses (kstep0, buffer0)
    const int blk = lane >> 3, rr = lane & 7;
    uint32_t addrA[2], addrB[4];
    #pragma unroll
    for (int mt = 0; mt < 2; mt++) {
        int m = wm * 32 + mt * 16 + (blk & 1) * 8 + rr;
        addrA[mt] = sbase + m * 64 + (((blk >> 1) ^ (m & 3)) << 4);
    }
    #pragma unroll
    for (int nt2 = 0; nt2 < 4; nt2++) {
        int n = wn * 64 + nt2 * 16 + (blk & 1) * 8 + rr;
        addrB[nt2] = sbase + 8192 + n * 64 + (((blk >> 1) ^ (n & 3)) << 4);
    }

    float acc[2][8][4] = {};

    load_chunk(0, 0); CPC();
    load_chunk(1, 16384u); CPC();

    // Fully unrolled: buffer offsets and prefetch indices are compile-time.
    #pragma unroll
    for (int c = 0; c < NCH; c++) {
        CPW(1);                                   // chunk c landed (FIFO)
        __syncthreads();                          // all warps done with chunk c-1
        if (c + 2 < NCH)
            load_chunk(c + 2, (uint32_t)(((c + 2) % 3) * 16384));
        CPC();                                    // one group per iteration

        const uint32_t bo = (uint32_t)((c % 3) * 16384);
        #pragma unroll
        for (int kstep = 0; kstep < 2; kstep++) {
            const uint32_t kx = kstep * 32;       // XOR: flips swizzle-group bit1
            uint32_t a[2][4];
            #pragma unroll
            for (int mt = 0; mt < 2; mt++)
                LDSM4(a[mt], (addrA[mt] + bo) ^ kx);
            #pragma unroll
            for (int nt2 = 0; nt2 < 4; nt2++) {
                uint32_t r[4];
                LDSM4(r, (addrB[nt2] + bo) ^ kx);
                #pragma unroll
                for (int mt = 0; mt < 2; mt++) {
                    MMA16816(acc[mt][nt2 * 2 + 0], a[mt], r[0], r[2]);
                    MMA16816(acc[mt][nt2 * 2 + 1], a[mt], r[1], r[3]);
                }
            }
        }
    }

    const int tq = lane >> 2, tr = lane & 3;

    if (MODE == 0) {
        // Per-seg (o-block) offsets: computed ONCE (independent of col/pass).
        size_t segoff[4];
        #pragma unroll
        for (int seg = 0; seg < 4; seg++) {
            int o0 = ot * 128 + seg * 32;
            int qi = o0 / CDIM;
            int head = (o0 % CDIM) >> 5;
            segoff[seg] = (size_t)qi * QS + (size_t)head * (NTOK * DHEAD) + lane;
        }
        // Stage to smem, then coalesced 128B scatter into windowed layout.
        float* sf = (float*)smem;
        #pragma unroll
        for (int pass = 0; pass < 2; pass++) {
            __syncthreads();
            if (wn == pass) {
                #pragma unroll
                for (int mt = 0; mt < 2; mt++)
                    #pragma unroll
                    for (int nt = 0; nt < 8; nt++) {
                        int row = wm * 32 + mt * 16 + tq;
                        int col = nt * 8 + tr * 2;
                        sf[row * 65 + col]           = acc[mt][nt][0];
                        sf[row * 65 + col + 1]       = acc[mt][nt][1];
                        sf[(row + 8) * 65 + col]     = acc[mt][nt][2];
                        sf[(row + 8) * 65 + col + 1] = acc[mt][nt][3];
                    }
            }
            __syncthreads();
            // 8 cols/thread; pixel decomposition ONCE per col (not per seg)
            #pragma unroll
            for (int cc = 0; cc < 8; cc++) {
                int col = w + 8 * cc;             // 0..63
                int p = pt * 128 + pass * 64 + col;
                if (p < NPIX) {
                    int y = p / HW, xx = p % HW;
                    int win = b * 64 + (y / WS) * 8 + xx / WS;
                    int tok = (y % WS) * WS + xx % WS;
                    size_t pbase = (size_t)win * (NHEAD * NTOK * DHEAD)
                                 + (size_t)tok * DHEAD;
                    #pragma unroll
                    for (int seg = 0; seg < 4; seg++)
                        g_qkv[segoff[seg] + pbase] = sf[(seg * 32 + lane) * 65 + col];
                }
            }
        }
    } else {
        #pragma unroll
        for (int mt = 0; mt < 2; mt++) {
            int o = ot * 128 + wm * 32 + mt * 16 + tq;
            float bias0 = __ldg(b_proj + o);
            float bias8 = __ldg(b_proj + o + 8);
            float* r0 = out + ((size_t)b * CDIM + o) * NPIX;
            float* r8 = r0 + (size_t)8 * NPIX;
            #pragma unroll
            for (int nt = 0; nt < 8; nt++) {
                int p = pt * 128 + wn * 64 + nt * 8 + tr * 2;
                if (p < NPIX) {
                    *(float2*)(r0 + p) = make_float2(acc[mt][nt][0] + bias0,
                                                     acc[mt][nt][1] + bias0);
                    *(float2*)(r8 + p) = make_float2(acc[mt][nt][2] + bias8,
                                                     acc[mt][nt][3] + bias8);
                }
            }
        }
    }
}

// ---------------------------------------------------------------------------
// attention: fp32 windowed in, fp16 transposed out (g_attT).
// Register-tiled 4x4 micro-GEMMs; q/k transposed in smem for LDS.128.
// ---------------------------------------------------------------------------
__global__ __launch_bounds__(128) void attn_kernel(const float* __restrict__ bias_table)
{
    const int wh   = blockIdx.x;
    const int win  = wh / NHEAD;
    const int head = wh % NHEAD;
    const int tid  = threadIdx.x;

    __shared__ float qT[32 * 56];     // [d][tok], cols 49..55 zero
    __shared__ float kT[32 * 56];
    __shared__ float vs[NTOK * 32];   // [tok][d]
    __shared__ float s[52 * 53];      // logits / probs, stride 53
    __shared__ float sbias[169];

    const float scale = 0.17677669529663687f;
    const size_t base = (((size_t)win * NHEAD + head) * NTOK) * DHEAD;
    const float4* qp = (const float4*)(g_qkv + base);
    const float4* kp = (const float4*)(g_qkv + QS + base);
    const float4* vp = (const float4*)(g_qkv + 2 * QS + base);

    // zero pad columns 49..55 of qT, kT (read by i0=48 tiles)
    for (int e = tid; e < 448; e += 128) {
        int a = e / 224, rem = e % 224;
        int r = rem / 7, c = 49 + rem % 7;
        (a ? kT : qT)[r * 56 + c] = 0.f;
    }
    for (int e = tid; e < 169; e += 128)
        sbias[e] = bias_table[e * NHEAD + head];

    for (int e = tid; e < 392; e += 128) {
        int tok = e >> 3, d4 = (e & 7) * 4;
        float4 q4 = qp[e];
        qT[(d4 + 0) * 56 + tok] = q4.x * scale;
        qT[(d4 + 1) * 56 + tok] = q4.y * scale;
        qT[(d4 + 2) * 56 + tok] = q4.z * scale;
        qT[(d4 + 3) * 56 + tok] = q4.w * scale;
        float4 k4 = kp[e];
        kT[(d4 + 0) * 56 + tok] = k4.x;
        kT[(d4 + 1) * 56 + tok] = k4.y;
        kT[(d4 + 2) * 56 + tok] = k4.z;
        kT[(d4 + 3) * 56 + tok] = k4.w;
        ((float4*)vs)[e] = vp[e];
    }
    __syncthreads();

    // S = (q^T)^T (k^T): 13x13 tiles of 4x4; 2 x LDS.128 per 16 FMA
    for (int t = tid; t < 169; t += 128) {
        const int i0 = (t / 13) * 4, j0 = (t % 13) * 4;
        float acc[4][4] = {};
        #pragma unroll
        for (int d = 0; d < 32; d++) {
            float4 q4 = *(const float4*)&qT[d * 56 + i0];
            float4 k4 = *(const float4*)&kT[d * 56 + j0];
            float qa[4] = {q4.x, q4.y, q4.z, q4.w};
            float ka[4] = {k4.x, k4.y, k4.z, k4.w};
            #pragma unroll
            for (int ii = 0; ii < 4; ii++)
                #pragma unroll
                for (int jj = 0; jj < 4; jj++)
                    acc[ii][jj] += qa[ii] * ka[jj];
        }
        #pragma unroll
        for (int ii = 0; ii < 4; ii++) {
            int i = i0 + ii;
            #pragma unroll
            for (int jj = 0; jj < 4; jj++) {
                int j = j0 + jj;
                float v = 0.f;
                if (i < NTOK && j < NTOK) {
                    int bidx = (i / WS - j / WS + 6) * 13 + (i % WS - j % WS + 6);
                    v = acc[ii][jj] + sbias[bidx];
                }
                s[i * 53 + j] = v;
            }
        }
    }
    __syncthreads();

    if (tid < NTOK) {
        float m = -1e30f;
        #pragma unroll
        for (int j = 0; j < NTOK; j++) m = fmaxf(m, s[tid * 53 + j]);
        float sum = 0.f;
        #pragma unroll
        for (int j = 0; j < NTOK; j++) {
            float ev = __expf(s[tid * 53 + j] - m);
            s[tid * 53 + j] = ev;
            sum += ev;
        }
        float inv = 1.f / sum;
        #pragma unroll
        for (int j = 0; j < NTOK; j++) s[tid * 53 + j] *= inv;
    }
    __syncthreads();

    // O = P @ V: 13 i-tiles x 8 d-quads = 104 threads, 4x4 register tiles
    if (tid < 104) {
        const int i0 = (tid >> 3) * 4, d0 = (tid & 7) * 4;
        float acc[4][4] = {};
        #pragma unroll 7
        for (int m = 0; m < NTOK; m++) {
            float4 v4 = *(const float4*)&vs[m * 32 + d0];
            float va[4] = {v4.x, v4.y, v4.z, v4.w};
            float sa[4];
            #pragma unroll
            for (int ii = 0; ii < 4; ii++) sa[ii] = s[(i0 + ii) * 53 + m];
            #pragma unroll
            for (int ii = 0; ii < 4; ii++)
                #pragma unroll
                for (int jj = 0; jj < 4; jj++)
                    acc[ii][jj] += sa[ii] * va[jj];
        }

        const int b_img = win >> 6;
        const int wl = win & 63;
        const int wy = wl >> 3, wx = wl & 7;
        #pragma unroll
        for (int ii = 0; ii < 4; ii++) {
            int i = i0 + ii;
            if (i < NTOK) {
                int y  = wy * WS + i / WS;
                int xx = wx * WS + i % WS;
                __half* row = g_attT
                    + ((size_t)b_img * NPIXP + y * HW + xx) * KS + head * DHEAD + d0;
                *(__half2*)(row)     = __floats2half2_rn(acc[ii][0], acc[ii][1]);
                *(__half2*)(row + 2) = __floats2half2_rn(acc[ii][2], acc[ii][3]);
            }
        }
    }
}

// ---------------------------------------------------------------------------
extern "C" void kernel_launch(void* const* d_in, const int* in_sizes, int n_in,
                              void* d_out, int out_size)
{
    const float* x          = (const float*)d_in[0];
    const float* w_qkv      = (const float*)d_in[1];
    const float* bias_table = (const float*)d_in[2];
    const float* w_proj     = (const float*)d_in[3];
    const float* b_proj     = (const float*)d_in[4];
    float* out = (float*)d_out;

    conv_w_kernel<<<(1152 * (KS / 2) + 255) / 256, 256>>>(w_qkv, 0, 1152);
    conv_w_kernel<<<(384 * (KS / 2) + 255) / 256, 256>>>(w_proj, 1, 384);
    conv_x_kernel<<<dim3(NPIX / 32, BATCH), 256>>>(x);

    gemm_kernel<0><<<dim3(NPIXP / 128, 9, BATCH), 256>>>(nullptr, nullptr);

    attn_kernel<<<NWIN * NHEAD, 128>>>(bias_table);

    gemm_kernel<1><<<dim3(NPIXP / 128, 3, BATCH), 256>>>(b_proj, out);
}

// round 15
// speedup vs baseline: 2.0101x; 1.0024x over previous
#include <cuda_runtime.h>
#include <cuda_fp16.h>
#include <cstdint>

// ---------------------------------------------------------------------------
// Problem constants
// ---------------------------------------------------------------------------
#define BATCH 32
#define CDIM 384
#define HW 56
#define NPIX 3136
#define NPIXP 3200         // padded pixel count (25 * 128)
#define WS 7
#define NHEAD 12
#define DHEAD 32
#define NWIN 2048
#define NTOK 49
#define KS 384             // single fp16 GEMM K
#define NCH 12             // KS / 32 chunks

#define QS ((size_t)NWIN * NHEAD * NTOK * DHEAD)

// Scratch (device globals are zero-initialized; padding rows read as 0)
__device__ float   g_qkv[3 * NWIN * NHEAD * NTOK * DHEAD];   // 462 MB
__device__ __half  g_wq[(3 * CDIM) * KS];
__device__ __half  g_wp[CDIM * KS];
__device__ __half  g_xT[(size_t)BATCH * NPIXP * KS];         // 77 MB
__device__ __half  g_attT[(size_t)BATCH * NPIXP * KS];       // 77 MB

// ---------------------------------------------------------------------------
// PTX helpers (base-target instructions only: sm_80-era)
// ---------------------------------------------------------------------------
__device__ __forceinline__ uint32_t smem_u32(const void* p) {
    uint32_t a;
    asm("{ .reg .u64 t; cvta.to.shared.u64 t, %1; cvt.u32.u64 %0, t; }" : "=r"(a) : "l"(p));
    return a;
}
#define CPA(dst, src) \
    asm volatile("cp.async.cg.shared.global [%0], [%1], 16;" :: "r"(dst), "l"(src))
#define CPC() asm volatile("cp.async.commit_group;" ::: "memory")
#define CPW(n) asm volatile("cp.async.wait_group %0;" :: "n"(n) : "memory")

#define LDSM4(r, addr) \
    asm volatile("ldmatrix.sync.aligned.m8n8.x4.shared.b16 {%0,%1,%2,%3}, [%4];" \
        : "=r"((r)[0]), "=r"((r)[1]), "=r"((r)[2]), "=r"((r)[3]) : "r"(addr))

#define MMA16816(d, a, b0, b1) \
    asm volatile("mma.sync.aligned.m16n8k16.row.col.f32.f16.f16.f32 " \
        "{%0,%1,%2,%3}, {%4,%5,%6,%7}, {%8,%9}, {%0,%1,%2,%3};" \
        : "+f"((d)[0]), "+f"((d)[1]), "+f"((d)[2]), "+f"((d)[3]) \
        : "r"((a)[0]), "r"((a)[1]), "r"((a)[2]), "r"((a)[3]), "r"(b0), "r"(b1))

// ---------------------------------------------------------------------------
// conv_w: fp32 weight [rows][384] -> fp16, same layout.
// which==0 -> g_wq (1152 rows), which==1 -> g_wp (384 rows)
// ---------------------------------------------------------------------------
__global__ __launch_bounds__(256) void conv_w_kernel(const float* __restrict__ w,
                                                     int which, int rows)
{
    int idx = blockIdx.x * 256 + threadIdx.x;
    int total = rows * (KS / 2);
    if (idx >= total) return;
    const float2 v = *(const float2*)(w + idx * 2);
    __half* dst = which ? g_wp : g_wq;
    *(__half2*)(dst + idx * 2) = __floats2half2_rn(v.x, v.y);
}

// ---------------------------------------------------------------------------
// conv_x: x[b][c][p] (fp32) -> g_xT[b][p][c] (fp16 transposed)
// block tile: 32 pixels x 384 channels (two passes of 192c through smem)
// ---------------------------------------------------------------------------
__global__ __launch_bounds__(256) void conv_x_kernel(const float* __restrict__ x)
{
    __shared__ float s[192 * 36];
    const int b  = blockIdx.y;
    const int p0 = blockIdx.x * 32;
    const int tid = threadIdx.x;
    const int pp = tid >> 3, ct = tid & 7;

    __half* my = g_xT + ((size_t)b * NPIXP + p0 + pp) * KS;

    for (int pass = 0; pass < 2; pass++) {
        const int c0 = pass * 192;
        __syncthreads();
        #pragma unroll
        for (int i = 0; i < 6; i++) {
            int e = tid + i * 256;
            int row = e >> 3, c4 = e & 7;
            float4 v = *(const float4*)(x + ((size_t)(b * CDIM + c0 + row)) * NPIX + p0 + c4 * 4);
            *(float4*)&s[row * 36 + c4 * 4] = v;
        }
        __syncthreads();
        for (int cp = ct; cp < 96; cp += 8) {
            int sl = 2 * cp;
            float v0 = s[sl * 36 + pp];
            float v1 = s[(sl + 1) * 36 + pp];
            *(__half2*)(my + c0 + sl) = __floats2half2_rn(v0, v1);
        }
    }
}

// ---------------------------------------------------------------------------
// mma.sync GEMM: D[128 o][128 p] = A[o][k] B[p][k], K=384, fp16 in, fp32 acc.
// 256 threads = 8 warps (4m x 2n), warp tile 32x64 = 2x8 m16n8k16 mma.
// Fully-unrolled 12-chunk mainloop, 3-stage cp.async pipeline, 2 CTAs/SM.
// MODE 0: A=g_wq, B=g_xT,   epilogue -> windowed fp32 qkv scatter (via smem)
// MODE 1: A=g_wp, B=g_attT, epilogue -> out + bias (direct)
// ---------------------------------------------------------------------------
template <int MODE>
__global__ __launch_bounds__(256, 2) void gemm_kernel(const float* __restrict__ b_proj,
                                                      float* __restrict__ out)
{
    __shared__ __align__(128) char smem[49152];   // 3 x (8K A + 8K B); epi 128x65 f32

    const int b   = blockIdx.z;
    const int pt  = blockIdx.x;
    const int ot  = blockIdx.y;
    const int tid = threadIdx.x;
    const int lane = tid & 31, w = tid >> 5;
    const int wm = w >> 1, wn = w & 1;

    const uint32_t sbase = smem_u32(smem);

    const __half* Ag = (MODE == 0 ? g_wq : g_wp) + (size_t)(ot * 128) * KS;
    const __half* Bg = (MODE == 0 ? g_xT : g_attT)
                       + ((size_t)b * NPIXP + (size_t)pt * 128) * KS;

    // loader mapping: 512 16B groups per tile, 2 per thread (rows r, r+64)
    const int lr = tid >> 2, lg = tid & 3;
    const uint32_t sA = sbase + lr * 64 + ((lg ^ (lr & 3)) << 4);
    const uint32_t sB = sA + 8192;
    const __half* Asrc = Ag + (size_t)lr * KS + lg * 8;
    const __half* Bsrc = Bg + (size_t)lr * KS + lg * 8;

    auto load_chunk = [&](int c, uint32_t bo) {
        const __half* a = Asrc + c * 32;
        CPA(sA + bo, a);
        CPA(sA + bo + 4096, a + (size_t)64 * KS);
        const __half* bb = Bsrc + c * 32;
        CPA(sB + bo, bb);
        CPA(sB + bo + 4096, bb + (size_t)64 * KS);
    };

    // ldmatrix per-thread base addresses (kstep0, buffer0)
    const int blk = lane >> 3, rr = lane & 7;
    uint32_t addrA[2], addrB[4];
    #pragma unroll
    for (int mt = 0; mt < 2; mt++) {
        int m = wm * 32 + mt * 16 + (blk & 1) * 8 + rr;
        addrA[mt] = sbase + m * 64 + (((blk >> 1) ^ (m & 3)) << 4);
    }
    #pragma unroll
    for (int nt2 = 0; nt2 < 4; nt2++) {
        int n = wn * 64 + nt2 * 16 + (blk & 1) * 8 + rr;
        addrB[nt2] = sbase + 8192 + n * 64 + (((blk >> 1) ^ (n & 3)) << 4);
    }

    float acc[2][8][4] = {};

    load_chunk(0, 0); CPC();
    load_chunk(1, 16384u); CPC();

    // Fully unrolled: buffer offsets and prefetch indices are compile-time.
    #pragma unroll
    for (int c = 0; c < NCH; c++) {
        CPW(1);                                   // chunk c landed (FIFO)
        __syncthreads();                          // all warps done with chunk c-1
        if (c + 2 < NCH)
            load_chunk(c + 2, (uint32_t)(((c + 2) % 3) * 16384));
        CPC();                                    // one group per iteration

        const uint32_t bo = (uint32_t)((c % 3) * 16384);
        #pragma unroll
        for (int kstep = 0; kstep < 2; kstep++) {
            const uint32_t kx = kstep * 32;       // XOR: flips swizzle-group bit1
            uint32_t a[2][4];
            #pragma unroll
            for (int mt = 0; mt < 2; mt++)
                LDSM4(a[mt], (addrA[mt] + bo) ^ kx);
            #pragma unroll
            for (int nt2 = 0; nt2 < 4; nt2++) {
                uint32_t r[4];
                LDSM4(r, (addrB[nt2] + bo) ^ kx);
                #pragma unroll
                for (int mt = 0; mt < 2; mt++) {
                    MMA16816(acc[mt][nt2 * 2 + 0], a[mt], r[0], r[2]);
                    MMA16816(acc[mt][nt2 * 2 + 1], a[mt], r[1], r[3]);
                }
            }
        }
    }

    const int tq = lane >> 2, tr = lane & 3;

    if (MODE == 0) {
        // Per-seg (o-block) offsets: computed ONCE (independent of col/pass).
        size_t segoff[4];
        #pragma unroll
        for (int seg = 0; seg < 4; seg++) {
            int o0 = ot * 128 + seg * 32;
            int qi = o0 / CDIM;
            int head = (o0 % CDIM) >> 5;
            segoff[seg] = (size_t)qi * QS + (size_t)head * (NTOK * DHEAD) + lane;
        }
        // Stage to smem, then coalesced 128B scatter into windowed layout.
        float* sf = (float*)smem;
        #pragma unroll
        for (int pass = 0; pass < 2; pass++) {
            __syncthreads();
            if (wn == pass) {
                #pragma unroll
                for (int mt = 0; mt < 2; mt++)
                    #pragma unroll
                    for (int nt = 0; nt < 8; nt++) {
                        int row = wm * 32 + mt * 16 + tq;
                        int col = nt * 8 + tr * 2;
                        sf[row * 65 + col]           = acc[mt][nt][0];
                        sf[row * 65 + col + 1]       = acc[mt][nt][1];
                        sf[(row + 8) * 65 + col]     = acc[mt][nt][2];
                        sf[(row + 8) * 65 + col + 1] = acc[mt][nt][3];
                    }
            }
            __syncthreads();
            // 8 cols/thread; pixel decomposition ONCE per col (not per seg)
            #pragma unroll
            for (int cc = 0; cc < 8; cc++) {
                int col = w + 8 * cc;             // 0..63
                int p = pt * 128 + pass * 64 + col;
                if (p < NPIX) {
                    int y = p / HW, xx = p % HW;
                    int win = b * 64 + (y / WS) * 8 + xx / WS;
                    int tok = (y % WS) * WS + xx % WS;
                    size_t pbase = (size_t)win * (NHEAD * NTOK * DHEAD)
                                 + (size_t)tok * DHEAD;
                    #pragma unroll
                    for (int seg = 0; seg < 4; seg++)
                        g_qkv[segoff[seg] + pbase] = sf[(seg * 32 + lane) * 65 + col];
                }
            }
        }
    } else {
        #pragma unroll
        for (int mt = 0; mt < 2; mt++) {
            int o = ot * 128 + wm * 32 + mt * 16 + tq;
            float bias0 = __ldg(b_proj + o);
            float bias8 = __ldg(b_proj + o + 8);
            float* r0 = out + ((size_t)b * CDIM + o) * NPIX;
            float* r8 = r0 + (size_t)8 * NPIX;
            #pragma unroll
            for (int nt = 0; nt < 8; nt++) {
                int p = pt * 128 + wn * 64 + nt * 8 + tr * 2;
                if (p < NPIX) {
                    *(float2*)(r0 + p) = make_float2(acc[mt][nt][0] + bias0,
                                                     acc[mt][nt][1] + bias0);
                    *(float2*)(r8 + p) = make_float2(acc[mt][nt][2] + bias8,
                                                     acc[mt][nt][3] + bias8);
                }
            }
        }
    }
}

// ---------------------------------------------------------------------------
// attention: fp32 windowed in, fp16 transposed out (g_attT).
// Register-tiled 4x4 micro-GEMMs; q/k transposed in smem for LDS.128.
// ---------------------------------------------------------------------------
__global__ __launch_bounds__(128) void attn_kernel(const float* __restrict__ bias_table)
{
    const int wh   = blockIdx.x;
    const int win  = wh / NHEAD;
    const int head = wh % NHEAD;
    const int tid  = threadIdx.x;

    __shared__ float qT[32 * 56];     // [d][tok], cols 49..55 zero
    __shared__ float kT[32 * 56];
    __shared__ float vs[NTOK * 32];   // [tok][d]
    __shared__ float s[52 * 53];      // logits / probs, stride 53
    __shared__ float sbias[169];

    const float scale = 0.17677669529663687f;
    const size_t base = (((size_t)win * NHEAD + head) * NTOK) * DHEAD;
    const float4* qp = (const float4*)(g_qkv + base);
    const float4* kp = (const float4*)(g_qkv + QS + base);
    const float4* vp = (const float4*)(g_qkv + 2 * QS + base);

    // zero pad columns 49..55 of qT, kT (read by i0=48 tiles)
    for (int e = tid; e < 448; e += 128) {
        int a = e / 224, rem = e % 224;
        int r = rem / 7, c = 49 + rem % 7;
        (a ? kT : qT)[r * 56 + c] = 0.f;
    }
    for (int e = tid; e < 169; e += 128)
        sbias[e] = bias_table[e * NHEAD + head];

    for (int e = tid; e < 392; e += 128) {
        int tok = e >> 3, d4 = (e & 7) * 4;
        float4 q4 = qp[e];
        qT[(d4 + 0) * 56 + tok] = q4.x * scale;
        qT[(d4 + 1) * 56 + tok] = q4.y * scale;
        qT[(d4 + 2) * 56 + tok] = q4.z * scale;
        qT[(d4 + 3) * 56 + tok] = q4.w * scale;
        float4 k4 = kp[e];
        kT[(d4 + 0) * 56 + tok] = k4.x;
        kT[(d4 + 1) * 56 + tok] = k4.y;
        kT[(d4 + 2) * 56 + tok] = k4.z;
        kT[(d4 + 3) * 56 + tok] = k4.w;
        ((float4*)vs)[e] = vp[e];
    }
    __syncthreads();

    // S = (q^T)^T (k^T): 13x13 tiles of 4x4; 2 x LDS.128 per 16 FMA
    for (int t = tid; t < 169; t += 128) {
        const int i0 = (t / 13) * 4, j0 = (t % 13) * 4;
        float acc[4][4] = {};
        #pragma unroll
        for (int d = 0; d < 32; d++) {
            float4 q4 = *(const float4*)&qT[d * 56 + i0];
            float4 k4 = *(const float4*)&kT[d * 56 + j0];
            float qa[4] = {q4.x, q4.y, q4.z, q4.w};
            float ka[4] = {k4.x, k4.y, k4.z, k4.w};
            #pragma unroll
            for (int ii = 0; ii < 4; ii++)
                #pragma unroll
                for (int jj = 0; jj < 4; jj++)
                    acc[ii][jj] += qa[ii] * ka[jj];
        }
        #pragma unroll
        for (int ii = 0; ii < 4; ii++) {
            int i = i0 + ii;
            #pragma unroll
            for (int jj = 0; jj < 4; jj++) {
                int j = j0 + jj;
                float v = 0.f;
                if (i < NTOK && j < NTOK) {
                    int bidx = (i / WS - j / WS + 6) * 13 + (i % WS - j % WS + 6);
                    v = acc[ii][jj] + sbias[bidx];
                }
                s[i * 53 + j] = v;
            }
        }
    }
    __syncthreads();

    if (tid < NTOK) {
        float m = -1e30f;
        #pragma unroll
        for (int j = 0; j < NTOK; j++) m = fmaxf(m, s[tid * 53 + j]);
        float sum = 0.f;
        #pragma unroll
        for (int j = 0; j < NTOK; j++) {
            float ev = __expf(s[tid * 53 + j] - m);
            s[tid * 53 + j] = ev;
            sum += ev;
        }
        float inv = 1.f / sum;
        #pragma unroll
        for (int j = 0; j < NTOK; j++) s[tid * 53 + j] *= inv;
    }
    __syncthreads();

    // O = P @ V: 13 i-tiles x 8 d-quads = 104 threads, 4x4 register tiles
    if (tid < 104) {
        const int i0 = (tid >> 3) * 4, d0 = (tid & 7) * 4;
        float acc[4][4] = {};
        #pragma unroll 7
        for (int m = 0; m < NTOK; m++) {
            float4 v4 = *(const float4*)&vs[m * 32 + d0];
            float va[4] = {v4.x, v4.y, v4.z, v4.w};
            float sa[4];
            #pragma unroll
            for (int ii = 0; ii < 4; ii++) sa[ii] = s[(i0 + ii) * 53 + m];
            #pragma unroll
            for (int ii = 0; ii < 4; ii++)
                #pragma unroll
                for (int jj = 0; jj < 4; jj++)
                    acc[ii][jj] += sa[ii] * va[jj];
        }

        const int b_img = win >> 6;
        const int wl = win & 63;
        const int wy = wl >> 3, wx = wl & 7;
        #pragma unroll
        for (int ii = 0; ii < 4; ii++) {
            int i = i0 + ii;
            if (i < NTOK) {
                int y  = wy * WS + i / WS;
                int xx = wx * WS + i % WS;
                __half* row = g_attT
                    + ((size_t)b_img * NPIXP + y * HW + xx) * KS + head * DHEAD + d0;
                *(__half2*)(row)     = __floats2half2_rn(acc[ii][0], acc[ii][1]);
                *(__half2*)(row + 2) = __floats2half2_rn(acc[ii][2], acc[ii][3]);
            }
        }
    }
}

// ---------------------------------------------------------------------------
extern "C" void kernel_launch(void* const* d_in, const int* in_sizes, int n_in,
                              void* d_out, int out_size)
{
    const float* x          = (const float*)d_in[0];
    const float* w_qkv      = (const float*)d_in[1];
    const float* bias_table = (const float*)d_in[2];
    const float* w_proj     = (const float*)d_in[3];
    const float* b_proj     = (const float*)d_in[4];
    float* out = (float*)d_out;

    conv_w_kernel<<<(1152 * (KS / 2) + 255) / 256, 256>>>(w_qkv, 0, 1152);
    conv_w_kernel<<<(384 * (KS / 2) + 255) / 256, 256>>>(w_proj, 1, 384);
    conv_x_kernel<<<dim3(NPIX / 32, BATCH), 256>>>(x);

    gemm_kernel<0><<<dim3(NPIXP / 128, 9, BATCH), 256>>>(nullptr, nullptr);

    attn_kernel<<<NWIN * NHEAD, 128>>>(bias_table);

    gemm_kernel<1><<<dim3(NPIXP / 128, 3, BATCH), 256>>>(b_proj, out);
}